// round 16
// baseline (speedup 1.0000x reference)
#include <cuda_runtime.h>
#include <math.h>
#include <stdint.h>

// Problem shape (fixed per reference)
#define NB     2
#define NSEQ   2048
#define DMODEL 1024
#define NINNER 1024
#define NH     16
#define NDH    64
#define MTOT   (NB * NSEQ)   // 4096

// Scratch (allocation-free rule: __device__ globals)
__device__ float g_Xr [MTOT * DMODEL];        // 16 MB  tf32-rounded X
__device__ float g_Q  [MTOT * NINNER];        // 16 MB  (pre-scaled, tf32-valued)
__device__ float g_KV [MTOT * 2 * NINNER];    // 32 MB  (tf32-valued)
__device__ float g_A  [MTOT * NINNER];        // 16 MB  (tf32-valued)
__device__ float g_WqT [NINNER * DMODEL];     // 4 MB   [N][K], scaled+rounded
__device__ float g_WkvT[2 * NINNER * DMODEL]; // 8 MB   [N][K], rounded
__device__ float g_WoT [DMODEL * NINNER];     // 4 MB   [N][K], rounded

// ===========================================================================
// Helpers (baseline PTX only — ptxas targets sm_103, no 'a' features)
// ===========================================================================
__device__ __forceinline__ uint32_t f2tf32(float x) {
    uint32_t u;
    asm("cvt.rna.tf32.f32 %0, %1;" : "=r"(u) : "f"(x));
    return u;
}
__device__ __forceinline__ uint32_t smem_u32(const void* p) {
    uint32_t a;
    asm("{ .reg .u64 t; cvta.to.shared.u64 t, %1; cvt.u32.u64 %0, t; }"
        : "=r"(a) : "l"(p));
    return a;
}
__device__ __forceinline__ void cpa16(uint32_t dst, const void* src) {
    asm volatile("cp.async.cg.shared.global [%0], [%1], 16;"
                 :: "r"(dst), "l"(src) : "memory");
}
#define CP_COMMIT() asm volatile("cp.async.commit_group;" ::: "memory")
#define CP_WAIT1()  asm volatile("cp.async.wait_group 1;" ::: "memory")
#define CP_WAIT0()  asm volatile("cp.async.wait_group 0;" ::: "memory")

// m16n8k8 tf32 mma, row.col, fp32 accumulate
__device__ __forceinline__ void mma8(float* d, const uint32_t* a,
                                     uint32_t b0, uint32_t b1) {
    asm volatile(
        "mma.sync.aligned.m16n8k8.row.col.f32.tf32.tf32.f32 "
        "{%0,%1,%2,%3}, {%4,%5,%6,%7}, {%8,%9}, {%0,%1,%2,%3};"
        : "+f"(d[0]), "+f"(d[1]), "+f"(d[2]), "+f"(d[3])
        : "r"(a[0]), "r"(a[1]), "r"(a[2]), "r"(a[3]), "r"(b0), "r"(b1));
}

// ===========================================================================
// elementwise tf32 round: out[i] = tf32(in[i])
// ===========================================================================
__global__ __launch_bounds__(256) void round_kernel(
    const float* __restrict__ in, float* __restrict__ out, int n)
{
    const int i = (blockIdx.x * 256 + threadIdx.x) * 4;
    if (i < n) {
        float4 v = *(const float4*)&in[i];
        uint4 u = { f2tf32(v.x), f2tf32(v.y), f2tf32(v.z), f2tf32(v.w) };
        *(uint4*)&out[i] = u;
    }
}

// ===========================================================================
// 32x32 tiled transpose with scale + tf32 round: out[C,R] = tf32(in[R,C]^T*s)
// ===========================================================================
__global__ void transpose_kernel(const float* __restrict__ in,
                                 float* __restrict__ out, int R, int C,
                                 float scale) {
    __shared__ float t[32][33];
    const int bx = blockIdx.x * 32;
    const int by = blockIdx.y * 32;
    #pragma unroll
    for (int i = 0; i < 32; i += 8)
        t[threadIdx.y + i][threadIdx.x] =
            in[(size_t)(by + threadIdx.y + i) * C + bx + threadIdx.x] * scale;
    __syncthreads();
    #pragma unroll
    for (int i = 0; i < 32; i += 8)
        out[(size_t)(bx + threadIdx.y + i) * R + by + threadIdx.x] =
            __uint_as_float(f2tf32(t[threadIdx.x][threadIdx.y + i]));
}

// ===========================================================================
// tf32 mma.sync GEMM: C[M,N] = A[M,K] @ Bt[N,K]^T (+bias)
// 128x128x32 CTA tile, 8 warps. 3-stage cp.async pipeline.
// ===========================================================================
#define GST 36
#define GSTW (128 * GST)
#define GSTAGEW (2 * GSTW)
#define GEMM_SMEM_BYTES (3 * GSTAGEW * 4)    // 110592

__global__ __launch_bounds__(256, 2) void gemm_mma(
    const float* __restrict__ A, const float* __restrict__ Bt,
    const float* __restrict__ bias, float* __restrict__ C,
    int M, int N, int K, int round_out)
{
    extern __shared__ uint32_t sm[];
    const uint32_t smb = smem_u32(sm);
    const int tid  = threadIdx.x;
    const int lane = tid & 31, wid = tid >> 5;
    const int gid  = lane >> 2, tig = lane & 3;
    const int warp_m = wid & 1, warp_n = wid >> 1;
    const int bm = blockIdx.y * 128;
    const int bn = blockIdx.x * 128;

    const int lrow = tid >> 3;
    const int lch  = (tid & 7) << 2;
    const float* Ap = A  + (size_t)(bm + lrow) * K + lch;
    const float* Bp = Bt + (size_t)(bn + lrow) * K + lch;
    const uint32_t dstoff = (uint32_t)(lrow * GST + lch) * 4;
    const int nkt = K / 32;

    #define G_ISSUE(st, k0) do {                                              \
        const uint32_t base_ = smb + (uint32_t)(st) * (GSTAGEW * 4);          \
        _Pragma("unroll")                                                     \
        for (int i_ = 0; i_ < 4; i_++) {                                      \
            cpa16(base_ + dstoff + (uint32_t)(i_ * 32 * GST * 4),             \
                  Ap + (size_t)(32 * i_) * K + (k0));                         \
            cpa16(base_ + (GSTW * 4) + dstoff + (uint32_t)(i_ * 32 * GST * 4),\
                  Bp + (size_t)(32 * i_) * K + (k0));                         \
        }                                                                     \
        CP_COMMIT();                                                          \
    } while (0)

    G_ISSUE(0, 0);
    G_ISSUE(1, 32);

    float acc[4][4][4] = {};

    for (int kt = 0; kt < nkt; kt++) {
        if (kt + 1 < nkt) { CP_WAIT1(); } else { CP_WAIT0(); }
        __syncthreads();
        if (kt + 2 < nkt) G_ISSUE((kt + 2) % 3, (kt + 2) * 32);

        const uint32_t* sA = sm + (kt % 3) * GSTAGEW;
        const uint32_t* sB = sA + GSTW;
        #pragma unroll
        for (int ks = 0; ks < 4; ks++) {
            const int col = ks * 8 + tig;
            uint32_t af[4][4];
            #pragma unroll
            for (int im = 0; im < 4; im++) {
                const int base = (warp_m * 64 + im * 16 + gid) * GST + col;
                af[im][0] = sA[base];
                af[im][1] = sA[base + 8 * GST];
                af[im][2] = sA[base + 4];
                af[im][3] = sA[base + 8 * GST + 4];
            }
            uint32_t bf[4][2];
            #pragma unroll
            for (int jn = 0; jn < 4; jn++) {
                const int nb = (warp_n * 32 + jn * 8 + gid) * GST + col;
                bf[jn][0] = sB[nb];
                bf[jn][1] = sB[nb + 4];
            }
            #pragma unroll
            for (int im = 0; im < 4; im++)
                #pragma unroll
                for (int jn = 0; jn < 4; jn++)
                    mma8(acc[im][jn], af[im], bf[jn][0], bf[jn][1]);
        }
    }
    #undef G_ISSUE

    #pragma unroll
    for (int im = 0; im < 4; im++) {
        const int row0 = bm + warp_m * 64 + im * 16 + gid;
        #pragma unroll
        for (int jn = 0; jn < 4; jn++) {
            const int col = bn + warp_n * 32 + jn * 8 + 2 * tig;
            float b0 = 0.f, b1 = 0.f;
            if (bias) { b0 = bias[col]; b1 = bias[col + 1]; }
            float2 v0 = { acc[im][jn][0] + b0, acc[im][jn][1] + b1 };
            float2 v1 = { acc[im][jn][2] + b0, acc[im][jn][3] + b1 };
            if (round_out) {
                v0.x = __uint_as_float(f2tf32(v0.x));
                v0.y = __uint_as_float(f2tf32(v0.y));
                v1.x = __uint_as_float(f2tf32(v1.x));
                v1.y = __uint_as_float(f2tf32(v1.y));
            }
            *(float2*)&C[(size_t)row0 * N + col]       = v0;
            *(float2*)&C[(size_t)(row0 + 8) * N + col] = v1;
        }
    }
}

// ===========================================================================
// tf32 mma.sync flash attention — R16: 32 Q-rows per warp (im=0,1).
// 256 threads (8 warps), CTA = 256 Q rows of one (b,h); 1 CTA/SM.
// Every K/V B-fragment LDS feeds TWO mma8 (im reuse) -> LDS/mma ~1.25
// (was ~2.3). KT=32, double-buffered cp.async, ONE barrier per iter
// (wait0 -> bar -> issue-next -> compute). Softmax/PV interleaved per
// key-column jn (jn == PV k-step at KT=32). Q pre-scaled by 0.125*log2e.
// smem: sQ/sP 256*68 + 2*(32*68 + 32*72) = 26368 words = 105472 B.
// ===========================================================================
#define KT  32
#define FST 68
#define VST 72
#define SQW    (256 * FST)             // 17408 words
#define STAGEW (KT * FST + KT * VST)   // 4480 words
#define FLASH_SMEM_BYTES ((SQW + 2 * STAGEW) * 4)   // 105472

__global__ __launch_bounds__(256, 1) void flash_mma(
    const float* __restrict__ Q, const float* __restrict__ KV,
    float* __restrict__ O)
{
    extern __shared__ uint32_t smf[];
    uint32_t* sQ = smf;                 // becomes sP after Q frags hoisted
    const uint32_t smb = smem_u32(smf);

    const int tid  = threadIdx.x;
    const int lane = tid & 31, wid = tid >> 5;
    const int gid  = lane >> 2, tig = lane & 3;
    const int wrow = wid * 32;
    const int q0   = blockIdx.x * 256;
    const int bh   = blockIdx.y;
    const int b    = bh >> 4;
    const int h    = bh & 15;

    const float* Qb = Q  + (size_t)b * NSEQ * NINNER     + (size_t)h * NDH;
    const float* Kb = KV + (size_t)b * NSEQ * 2 * NINNER + (size_t)h * NDH;
    const float* Vb = Kb + NINNER;
    float*       Ob = O  + (size_t)b * NSEQ * NINNER     + (size_t)h * NDH;

    const int qrow = tid >> 4;
    const int qc4  = (tid & 15) << 2;

    // ---- prologue: async-copy Q (group 0), then K/V tile 0 (group 1) ----
    #pragma unroll
    for (int i = 0; i < 16; i++) {
        const int row = qrow + 16 * i;
        cpa16(smb + (uint32_t)(row * FST + qc4) * 4,
              &Qb[(size_t)(q0 + row) * NINNER + qc4]);
    }
    CP_COMMIT();
    {
        const uint32_t kb0 = smb + SQW * 4;
        const uint32_t vb0 = kb0 + KT * FST * 4;
        #pragma unroll
        for (int i = 0; i < 2; i++) {
            const int row = qrow + 16 * i;
            const size_t g = (size_t)row * (2 * NINNER) + qc4;
            cpa16(kb0 + (uint32_t)(row * FST + qc4) * 4, &Kb[g]);
            cpa16(vb0 + (uint32_t)(row * VST + qc4) * 4, &Vb[g]);
        }
    }
    CP_COMMIT();
    CP_WAIT1();                        // Q done
    __syncthreads();

    // hoist Q fragments: 2 row-groups (im) x 8 k-steps
    uint32_t qf[2][8][4];
    #pragma unroll
    for (int im = 0; im < 2; im++) {
        const int base = (wrow + im * 16 + gid) * FST;
        #pragma unroll
        for (int ks = 0; ks < 8; ks++) {
            const int w = ks * 8 + tig;
            qf[im][ks][0] = sQ[base + w];
            qf[im][ks][1] = sQ[base + 8 * FST + w];
            qf[im][ks][2] = sQ[base + w + 4];
            qf[im][ks][3] = sQ[base + 8 * FST + w + 4];
        }
    }

    float o[2][8][4] = {};
    float mr[2][2], lr[2][2];
    #pragma unroll
    for (int im = 0; im < 2; im++) {
        mr[im][0] = -INFINITY; mr[im][1] = -INFINITY;
        lr[im][0] = 0.f;       lr[im][1] = 0.f;
    }
    const unsigned qmask = 0xFu << (lane & 28);

    int stage = 0;
    for (int j0 = 0; j0 < NSEQ; j0 += KT) {
        CP_WAIT0();        // tile j copy (issued last iter) complete
        __syncthreads();   // + all warps done reading the other stage
        if (j0 + KT < NSEQ) {
            const uint32_t kbn = smb + (SQW + (stage ^ 1) * STAGEW) * 4;
            const uint32_t vbn = kbn + KT * FST * 4;
            #pragma unroll
            for (int i = 0; i < 2; i++) {
                const int row = qrow + 16 * i;
                const size_t g = (size_t)(j0 + KT + row) * (2 * NINNER) + qc4;
                cpa16(kbn + (uint32_t)(row * FST + qc4) * 4, &Kb[g]);
                cpa16(vbn + (uint32_t)(row * VST + qc4) * 4, &Vb[g]);
            }
            CP_COMMIT();
        }

        const uint32_t* sK = smf + SQW + stage * STAGEW;
        const uint32_t* sV = sK + KT * FST;

        // S = Q @ K^T : 32 rows x 32 keys per warp; K frag shared by both im
        float s[2][4][4] = {};
        #pragma unroll
        for (int ks = 0; ks < 8; ks++) {
            #pragma unroll
            for (int jn = 0; jn < 4; jn++) {
                const int kb = (jn * 8 + gid) * FST + ks * 8 + tig;
                const uint32_t k0 = sK[kb], k1 = sK[kb + 4];
                mma8(s[0][jn], qf[0][ks], k0, k1);
                mma8(s[1][jn], qf[1][ks], k0, k1);
            }
        }

        // row max + rescale per im group
        float mn[2][2], al[2][2];
        #pragma unroll
        for (int im = 0; im < 2; im++) {
            float mx0 = -INFINITY, mx1 = -INFINITY;
            #pragma unroll
            for (int jn = 0; jn < 4; jn++) {
                mx0 = fmaxf(mx0, fmaxf(s[im][jn][0], s[im][jn][1]));
                mx1 = fmaxf(mx1, fmaxf(s[im][jn][2], s[im][jn][3]));
            }
            mx0 = fmaxf(mx0, __shfl_xor_sync(0xffffffffu, mx0, 1));
            mx0 = fmaxf(mx0, __shfl_xor_sync(0xffffffffu, mx0, 2));
            mx1 = fmaxf(mx1, __shfl_xor_sync(0xffffffffu, mx1, 1));
            mx1 = fmaxf(mx1, __shfl_xor_sync(0xffffffffu, mx1, 2));
            mn[im][0] = fmaxf(mr[im][0], mx0);
            mn[im][1] = fmaxf(mr[im][1], mx1);
            al[im][0] = exp2f(mr[im][0] - mn[im][0]);
            al[im][1] = exp2f(mr[im][1] - mn[im][1]);
            mr[im][0] = mn[im][0]; mr[im][1] = mn[im][1];
            #pragma unroll
            for (int dt = 0; dt < 8; dt++) {
                o[im][dt][0] *= al[im][0]; o[im][dt][1] *= al[im][0];
                o[im][dt][2] *= al[im][1]; o[im][dt][3] *= al[im][1];
            }
        }

        // interleaved softmax + PV, one key-column (8 keys) at a time
        float rs[2][2] = {};
        #pragma unroll
        for (int jn = 0; jn < 4; jn++) {
            #pragma unroll
            for (int im = 0; im < 2; im++) {
                const float p0 = exp2f(s[im][jn][0] - mn[im][0]);
                const float p1 = exp2f(s[im][jn][1] - mn[im][0]);
                const float p2 = exp2f(s[im][jn][2] - mn[im][1]);
                const float p3 = exp2f(s[im][jn][3] - mn[im][1]);
                rs[im][0] += p0 + p1;
                rs[im][1] += p2 + p3;
                const int pb = (wrow + im * 16 + gid) * FST + 2 * tig + jn * 8;
                uint2 w0 = { f2tf32(p0), f2tf32(p1) };
                uint2 w1 = { f2tf32(p2), f2tf32(p3) };
                *(uint2*)&sQ[pb]           = w0;   // sP overlays sQ
                *(uint2*)&sQ[pb + 8 * FST] = w1;
            }
            __syncwarp(qmask);          // P exchange is intra-quad
            uint32_t pa[2][4];
            #pragma unroll
            for (int im = 0; im < 2; im++) {
                const int base = (wrow + im * 16 + gid) * FST + jn * 8 + tig;
                pa[im][0] = sQ[base];
                pa[im][1] = sQ[base + 8 * FST];
                pa[im][2] = sQ[base + 4];
                pa[im][3] = sQ[base + 8 * FST + 4];
            }
            #pragma unroll
            for (int dt = 0; dt < 8; dt++) {
                const int vb = (jn * 8 + tig) * VST + dt * 8 + gid;
                const uint32_t v0 = sV[vb], v1 = sV[vb + 4 * VST];
                mma8(o[0][dt], pa[0], v0, v1);
                mma8(o[1][dt], pa[1], v0, v1);
            }
        }
        #pragma unroll
        for (int im = 0; im < 2; im++) {
            float r0 = rs[im][0], r1 = rs[im][1];
            r0 += __shfl_xor_sync(0xffffffffu, r0, 1);
            r0 += __shfl_xor_sync(0xffffffffu, r0, 2);
            r1 += __shfl_xor_sync(0xffffffffu, r1, 1);
            r1 += __shfl_xor_sync(0xffffffffu, r1, 2);
            lr[im][0] = lr[im][0] * al[im][0] + r0;
            lr[im][1] = lr[im][1] * al[im][1] + r1;
        }

        stage ^= 1;
    }

    // epilogue (tf32-rounded stores: out-proj GEMM consumes raw)
    #pragma unroll
    for (int im = 0; im < 2; im++) {
        const float inv0 = 1.0f / lr[im][0];
        const float inv1 = 1.0f / lr[im][1];
        const int r0 = q0 + wrow + im * 16 + gid;
        #pragma unroll
        for (int dt = 0; dt < 8; dt++) {
            const int col = dt * 8 + 2 * tig;
            uint2 v0 = { f2tf32(o[im][dt][0] * inv0), f2tf32(o[im][dt][1] * inv0) };
            uint2 v1 = { f2tf32(o[im][dt][2] * inv1), f2tf32(o[im][dt][3] * inv1) };
            *(uint2*)&Ob[(size_t)r0 * NINNER + col]       = v0;
            *(uint2*)&Ob[(size_t)(r0 + 8) * NINNER + col] = v1;
        }
    }
}

// ===========================================================================
extern "C" void kernel_launch(void* const* d_in, const int* in_sizes, int n_in,
                              void* d_out, int out_size)
{
    const float* X   = (const float*)d_in[0];
    const float* Wq  = (const float*)d_in[1];
    const float* Wkv = (const float*)d_in[2];
    const float* Wo  = (const float*)d_in[3];
    const float* bo  = (const float*)d_in[4];
    float* out = (float*)d_out;

    float *Xr, *Qb, *KVb, *Ab, *WqT, *WkvT, *WoT;
    cudaGetSymbolAddress((void**)&Xr,   g_Xr);
    cudaGetSymbolAddress((void**)&Qb,   g_Q);
    cudaGetSymbolAddress((void**)&KVb,  g_KV);
    cudaGetSymbolAddress((void**)&Ab,   g_A);
    cudaGetSymbolAddress((void**)&WqT,  g_WqT);
    cudaGetSymbolAddress((void**)&WkvT, g_WkvT);
    cudaGetSymbolAddress((void**)&WoT,  g_WoT);

    cudaFuncSetAttribute(gemm_mma, cudaFuncAttributeMaxDynamicSharedMemorySize,
                         GEMM_SMEM_BYTES);
    cudaFuncSetAttribute(flash_mma, cudaFuncAttributeMaxDynamicSharedMemorySize,
                         FLASH_SMEM_BYTES);

    // pre-round X to tf32 values (enables pure-cp.async GEMM loader)
    round_kernel<<<MTOT * DMODEL / 1024, 256>>>(X, Xr, MTOT * DMODEL);

    dim3 tb(32, 8);
    // WqT carries 0.125 * log2(e) so flash softmax can use exp2f
    transpose_kernel<<<dim3(NINNER / 32, DMODEL / 32), tb>>>(
        Wq,  WqT,  DMODEL, NINNER, 0.125f * 1.4426950408889634f);
    transpose_kernel<<<dim3(2 * NINNER / 32, DMODEL / 32), tb>>>(
        Wkv, WkvT, DMODEL, 2 * NINNER, 1.0f);
    transpose_kernel<<<dim3(DMODEL / 32, NINNER / 32), tb>>>(
        Wo,  WoT,  NINNER, DMODEL, 1.0f);

    // Q = (X @ Wq) * 0.125*log2e, tf32-rounded at store
    gemm_mma<<<dim3(NINNER / 128, MTOT / 128), 256, GEMM_SMEM_BYTES>>>(
        Xr, WqT, nullptr, Qb, MTOT, NINNER, DMODEL, 1);
    // KV = X @ Wkv, tf32-rounded at store
    gemm_mma<<<dim3(2 * NINNER / 128, MTOT / 128), 256, GEMM_SMEM_BYTES>>>(
        Xr, WkvT, nullptr, KVb, MTOT, 2 * NINNER, DMODEL, 1);
    // attention (stores tf32-rounded A): 256 rows/CTA
    flash_mma<<<dim3(NSEQ / 256, NB * NH), 256, FLASH_SMEM_BYTES>>>(Qb, KVb, Ab);
    // out = A @ Wo + bo (full fp32 store)
    gemm_mma<<<dim3(DMODEL / 128, MTOT / 128), 256, GEMM_SMEM_BYTES>>>(
        Ab, WoT, bo, out, MTOT, DMODEL, NINNER, 0);
}

// round 17
// speedup vs baseline: 1.0119x; 1.0119x over previous
#include <cuda_runtime.h>
#include <math.h>
#include <stdint.h>

// Problem shape (fixed per reference)
#define NB     2
#define NSEQ   2048
#define DMODEL 1024
#define NINNER 1024
#define NH     16
#define NDH    64
#define MTOT   (NB * NSEQ)   // 4096
#define FROWS  (3 * NINNER)  // 3072: fused QKV row stride

// Scratch (allocation-free rule: __device__ globals)
__device__ float g_Xr  [MTOT * DMODEL];         // 16 MB  tf32-rounded X
__device__ float g_QKV [MTOT * FROWS];          // 48 MB  [tok][Q|K|V]
__device__ float g_A   [MTOT * NINNER];         // 16 MB  (tf32-valued)
__device__ float g_Wqkv[FROWS * DMODEL];        // 12 MB  [N][K] fused weights
__device__ float g_WoT [DMODEL * NINNER];       //  4 MB  [N][K]

// ===========================================================================
// Helpers (baseline PTX only — ptxas targets sm_103, no 'a' features)
// ===========================================================================
__device__ __forceinline__ uint32_t f2tf32(float x) {
    uint32_t u;
    asm("cvt.rna.tf32.f32 %0, %1;" : "=r"(u) : "f"(x));
    return u;
}
__device__ __forceinline__ uint32_t smem_u32(const void* p) {
    uint32_t a;
    asm("{ .reg .u64 t; cvta.to.shared.u64 t, %1; cvt.u32.u64 %0, t; }"
        : "=r"(a) : "l"(p));
    return a;
}
__device__ __forceinline__ void cpa16(uint32_t dst, const void* src) {
    asm volatile("cp.async.cg.shared.global [%0], [%1], 16;"
                 :: "r"(dst), "l"(src) : "memory");
}
#define CP_COMMIT() asm volatile("cp.async.commit_group;" ::: "memory")
#define CP_WAIT1()  asm volatile("cp.async.wait_group 1;" ::: "memory")
#define CP_WAIT0()  asm volatile("cp.async.wait_group 0;" ::: "memory")

// m16n8k8 tf32 mma, row.col, fp32 accumulate
__device__ __forceinline__ void mma8(float* d, const uint32_t* a,
                                     uint32_t b0, uint32_t b1) {
    asm volatile(
        "mma.sync.aligned.m16n8k8.row.col.f32.tf32.tf32.f32 "
        "{%0,%1,%2,%3}, {%4,%5,%6,%7}, {%8,%9}, {%0,%1,%2,%3};"
        : "+f"(d[0]), "+f"(d[1]), "+f"(d[2]), "+f"(d[3])
        : "r"(a[0]), "r"(a[1]), "r"(a[2]), "r"(a[3]), "r"(b0), "r"(b1));
}
// ldmatrix x4 (b16 view of tf32 fragments; sm_75 baseline)
__device__ __forceinline__ void ldsm4(uint32_t* r, uint32_t addr) {
    asm volatile("ldmatrix.sync.aligned.m8n8.x4.shared.b16 {%0,%1,%2,%3}, [%4];"
        : "=r"(r[0]), "=r"(r[1]), "=r"(r[2]), "=r"(r[3]) : "r"(addr));
}

// ===========================================================================
// elementwise tf32 round: out[i] = tf32(in[i])
// ===========================================================================
__global__ __launch_bounds__(256) void round_kernel(
    const float* __restrict__ in, float* __restrict__ out, int n)
{
    const int i = (blockIdx.x * 256 + threadIdx.x) * 4;
    if (i < n) {
        float4 v = *(const float4*)&in[i];
        uint4 u = { f2tf32(v.x), f2tf32(v.y), f2tf32(v.z), f2tf32(v.w) };
        *(uint4*)&out[i] = u;
    }
}

// ===========================================================================
// 32x32 tiled transpose with scale + tf32 round: out[C,R] = tf32(in[R,C]^T*s)
// ===========================================================================
__global__ void transpose_kernel(const float* __restrict__ in,
                                 float* __restrict__ out, int R, int C,
                                 float scale) {
    __shared__ float t[32][33];
    const int bx = blockIdx.x * 32;
    const int by = blockIdx.y * 32;
    #pragma unroll
    for (int i = 0; i < 32; i += 8)
        t[threadIdx.y + i][threadIdx.x] =
            in[(size_t)(by + threadIdx.y + i) * C + bx + threadIdx.x] * scale;
    __syncthreads();
    #pragma unroll
    for (int i = 0; i < 32; i += 8)
        out[(size_t)(bx + threadIdx.y + i) * R + by + threadIdx.x] =
            __uint_as_float(f2tf32(t[threadIdx.x][threadIdx.y + i]));
}

// ===========================================================================
// tf32 mma.sync GEMM: C[M,N] = A[M,K] @ Bt[N,K]^T (+bias)
// 128x128x32 CTA tile, 8 warps, 3-stage cp.async pipeline.
// R17: fragment loads via ldmatrix.x4 — per k-iter loads 96 LDS -> 24 LDSM.
// ===========================================================================
#define GST 36
#define GSTW (128 * GST)
#define GSTAGEW (2 * GSTW)
#define GEMM_SMEM_BYTES (3 * GSTAGEW * 4)    // 110592

__global__ __launch_bounds__(256, 2) void gemm_mma(
    const float* __restrict__ A, const float* __restrict__ Bt,
    const float* __restrict__ bias, float* __restrict__ C,
    int M, int N, int K, int round_out)
{
    extern __shared__ uint32_t sm[];
    const uint32_t smb = smem_u32(sm);
    const int tid  = threadIdx.x;
    const int lane = tid & 31, wid = tid >> 5;
    const int gid  = lane >> 2, tig = lane & 3;
    const int warp_m = wid & 1, warp_n = wid >> 1;
    const int bm = blockIdx.y * 128;
    const int bn = blockIdx.x * 128;

    const int lrow = tid >> 3;
    const int lch  = (tid & 7) << 2;
    const float* Ap = A  + (size_t)(bm + lrow) * K + lch;
    const float* Bp = Bt + (size_t)(bn + lrow) * K + lch;
    const uint32_t dstoff = (uint32_t)(lrow * GST + lch) * 4;
    const int nkt = K / 32;

    // ldmatrix per-lane byte offsets (within A / B tile sections)
    // A tile im: rows warp_m*64+im*16 + (lane&7) + ((lane>>3)&1)*8,
    //            k-half = (lane>>4)&1  -> tiles order a0,a1,a2,a3
    uint32_t aoffL[4];
    #pragma unroll
    for (int im = 0; im < 4; im++) {
        const int row = warp_m * 64 + im * 16 + (lane & 7) + ((lane >> 3) & 1) * 8;
        aoffL[im] = (uint32_t)(row * GST + ((lane >> 4) & 1) * 4) * 4;
    }
    // B tile pair jp: rows warp_n*32+jp*16 + (lane&7) + ((lane>>4)&1)*8,
    //            k-half = (lane>>3)&1 -> tiles (jn0 h0, jn0 h1, jn1 h0, jn1 h1)
    uint32_t boffL[2];
    #pragma unroll
    for (int jp = 0; jp < 2; jp++) {
        const int row = warp_n * 32 + jp * 16 + (lane & 7) + ((lane >> 4) & 1) * 8;
        boffL[jp] = (uint32_t)(row * GST + ((lane >> 3) & 1) * 4) * 4;
    }

    #define G_ISSUE(st, k0) do {                                              \
        const uint32_t base_ = smb + (uint32_t)(st) * (GSTAGEW * 4);          \
        _Pragma("unroll")                                                     \
        for (int i_ = 0; i_ < 4; i_++) {                                      \
            cpa16(base_ + dstoff + (uint32_t)(i_ * 32 * GST * 4),             \
                  Ap + (size_t)(32 * i_) * K + (k0));                         \
            cpa16(base_ + (GSTW * 4) + dstoff + (uint32_t)(i_ * 32 * GST * 4),\
                  Bp + (size_t)(32 * i_) * K + (k0));                         \
        }                                                                     \
        CP_COMMIT();                                                          \
    } while (0)

    G_ISSUE(0, 0);
    G_ISSUE(1, 32);

    float acc[4][4][4] = {};

    for (int kt = 0; kt < nkt; kt++) {
        if (kt + 1 < nkt) { CP_WAIT1(); } else { CP_WAIT0(); }
        __syncthreads();
        if (kt + 2 < nkt) G_ISSUE((kt + 2) % 3, (kt + 2) * 32);

        const uint32_t abase = smb + (uint32_t)(kt % 3) * (GSTAGEW * 4);
        const uint32_t bbase = abase + GSTW * 4;
        #pragma unroll
        for (int ks = 0; ks < 4; ks++) {
            const uint32_t kb = (uint32_t)ks * 32;
            uint32_t af[4][4];
            #pragma unroll
            for (int im = 0; im < 4; im++)
                ldsm4(af[im], abase + aoffL[im] + kb);
            uint32_t bq[2][4];
            #pragma unroll
            for (int jp = 0; jp < 2; jp++)
                ldsm4(bq[jp], bbase + boffL[jp] + kb);
            #pragma unroll
            for (int im = 0; im < 4; im++)
                #pragma unroll
                for (int jp = 0; jp < 2; jp++) {
                    mma8(acc[im][jp * 2 + 0], af[im], bq[jp][0], bq[jp][1]);
                    mma8(acc[im][jp * 2 + 1], af[im], bq[jp][2], bq[jp][3]);
                }
        }
    }
    #undef G_ISSUE

    #pragma unroll
    for (int im = 0; im < 4; im++) {
        const int row0 = bm + warp_m * 64 + im * 16 + gid;
        #pragma unroll
        for (int jn = 0; jn < 4; jn++) {
            const int col = bn + warp_n * 32 + jn * 8 + 2 * tig;
            float b0 = 0.f, b1 = 0.f;
            if (bias) { b0 = bias[col]; b1 = bias[col + 1]; }
            float2 v0 = { acc[im][jn][0] + b0, acc[im][jn][1] + b1 };
            float2 v1 = { acc[im][jn][2] + b0, acc[im][jn][3] + b1 };
            if (round_out) {
                v0.x = __uint_as_float(f2tf32(v0.x));
                v0.y = __uint_as_float(f2tf32(v0.y));
                v1.x = __uint_as_float(f2tf32(v1.x));
                v1.y = __uint_as_float(f2tf32(v1.y));
            }
            *(float2*)&C[(size_t)row0 * N + col]       = v0;
            *(float2*)&C[(size_t)(row0 + 8) * N + col] = v1;
        }
    }
}

// ===========================================================================
// tf32 mma.sync flash attention (R15 config — best), fused-QKV stride 3072.
// 256 threads (8 warps), CTA = 128 Q rows of one (b,h); 2 CTAs/SM. KT=64.
// cp.async double-buffered K/V; softmax/PV interleaved in 4 chunks.
// ===========================================================================
#define KT  64
#define FST 68
#define VST 72
#define SQW    (128 * FST)
#define STAGEW (KT * FST + KT * VST)
#define FLASH_SMEM_BYTES ((SQW + 2 * STAGEW) * 4)   // 106496

__global__ __launch_bounds__(256, 2) void flash_mma(
    const float* __restrict__ QKV, float* __restrict__ O)
{
    extern __shared__ uint32_t smf[];
    uint32_t* sQ = smf;                 // becomes sP after Q frags hoisted
    const uint32_t smb = smem_u32(smf);

    const int tid  = threadIdx.x;
    const int lane = tid & 31, wid = tid >> 5;
    const int gid  = lane >> 2, tig = lane & 3;
    const int wrow = wid * 16;
    const int q0   = blockIdx.x * 128;
    const int bh   = blockIdx.y;
    const int b    = bh >> 4;
    const int h    = bh & 15;

    const float* Qb = QKV + (size_t)b * NSEQ * FROWS + (size_t)h * NDH;
    const float* Kb = Qb + NINNER;
    const float* Vb = Qb + 2 * NINNER;
    float*       Ob = O + (size_t)b * NSEQ * NINNER + (size_t)h * NDH;

    const int qrow = tid >> 4;
    const int qc4  = (tid & 15) << 2;

    // ---- prologue: async-copy Q (group 0), then K/V tile 0 (group 1) ----
    #pragma unroll
    for (int i = 0; i < 8; i++) {
        const int row = qrow + 16 * i;
        cpa16(smb + (uint32_t)(row * FST + qc4) * 4,
              &Qb[(size_t)(q0 + row) * FROWS + qc4]);
    }
    CP_COMMIT();
    {
        const uint32_t kb0 = smb + SQW * 4;
        const uint32_t vb0 = kb0 + KT * FST * 4;
        #pragma unroll
        for (int i = 0; i < 4; i++) {
            const int row = qrow + 16 * i;
            const size_t g = (size_t)row * FROWS + qc4;
            cpa16(kb0 + (uint32_t)(row * FST + qc4) * 4, &Kb[g]);
            cpa16(vb0 + (uint32_t)(row * VST + qc4) * 4, &Vb[g]);
        }
    }
    CP_COMMIT();
    CP_WAIT1();                        // Q done
    __syncthreads();

    // hoist Q fragments for all 8 k-steps (warp's own 16 rows)
    uint32_t qf[8][4];
    {
        const int base = (wrow + gid) * FST;
        #pragma unroll
        for (int ks = 0; ks < 8; ks++) {
            const int w = ks * 8 + tig;
            qf[ks][0] = sQ[base + w];
            qf[ks][1] = sQ[base + 8 * FST + w];
            qf[ks][2] = sQ[base + w + 4];
            qf[ks][3] = sQ[base + 8 * FST + w + 4];
        }
    }

    float o[8][4] = {};
    float mr0 = -INFINITY, mr1 = -INFINITY, lr0 = 0.f, lr1 = 0.f;
    const unsigned qmask = 0xFu << (lane & 28);

    int stage = 0;
    for (int j0 = 0; j0 < NSEQ; j0 += KT) {
        __syncthreads();
        if (j0 + KT < NSEQ) {
            const uint32_t kbn = smb + (SQW + (stage ^ 1) * STAGEW) * 4;
            const uint32_t vbn = kbn + KT * FST * 4;
            #pragma unroll
            for (int i = 0; i < 4; i++) {
                const int row = qrow + 16 * i;
                const size_t g = (size_t)(j0 + KT + row) * FROWS + qc4;
                cpa16(kbn + (uint32_t)(row * FST + qc4) * 4, &Kb[g]);
                cpa16(vbn + (uint32_t)(row * VST + qc4) * 4, &Vb[g]);
            }
            CP_COMMIT();
            CP_WAIT1();
        } else {
            CP_WAIT0();
        }
        __syncthreads();

        const uint32_t* sK = smf + SQW + stage * STAGEW;
        const uint32_t* sV = sK + KT * FST;

        // S = Q @ K^T  (16 rows x 64 keys per warp)
        float s[8][4] = {};
        #pragma unroll
        for (int ks = 0; ks < 8; ks++) {
            #pragma unroll
            for (int jn = 0; jn < 8; jn++) {
                const int kb = (jn * 8 + gid) * FST + ks * 8 + tig;
                mma8(s[jn], qf[ks], sK[kb], sK[kb + 4]);
            }
        }

        // row max
        float mx0 = -INFINITY, mx1 = -INFINITY;
        #pragma unroll
        for (int jn = 0; jn < 8; jn++) {
            mx0 = fmaxf(mx0, fmaxf(s[jn][0], s[jn][1]));
            mx1 = fmaxf(mx1, fmaxf(s[jn][2], s[jn][3]));
        }
        mx0 = fmaxf(mx0, __shfl_xor_sync(0xffffffffu, mx0, 1));
        mx0 = fmaxf(mx0, __shfl_xor_sync(0xffffffffu, mx0, 2));
        mx1 = fmaxf(mx1, __shfl_xor_sync(0xffffffffu, mx1, 1));
        mx1 = fmaxf(mx1, __shfl_xor_sync(0xffffffffu, mx1, 2));

        const float mn0 = fmaxf(mr0, mx0);
        const float mn1 = fmaxf(mr1, mx1);
        const float al0 = exp2f(mr0 - mn0);
        const float al1 = exp2f(mr1 - mn1);
        mr0 = mn0; mr1 = mn1;

        #pragma unroll
        for (int dt = 0; dt < 8; dt++) {
            o[dt][0] *= al0; o[dt][1] *= al0;
            o[dt][2] *= al1; o[dt][3] *= al1;
        }

        // interleaved softmax + PV, 4 chunks of 2 key-columns
        float rs0 = 0.f, rs1 = 0.f;
        const int pb0    = (wrow + gid) * FST + 2 * tig;
        const int pabase = (wrow + gid) * FST + tig;
        #pragma unroll
        for (int jp = 0; jp < 4; jp++) {
            #pragma unroll
            for (int u = 0; u < 2; u++) {
                const int jn = jp * 2 + u;
                const float p0 = exp2f(s[jn][0] - mn0);
                const float p1 = exp2f(s[jn][1] - mn0);
                const float p2 = exp2f(s[jn][2] - mn1);
                const float p3 = exp2f(s[jn][3] - mn1);
                rs0 += p0 + p1;
                rs1 += p2 + p3;
                uint2 w0 = { f2tf32(p0), f2tf32(p1) };
                uint2 w1 = { f2tf32(p2), f2tf32(p3) };
                *(uint2*)&sQ[pb0 + jn * 8]           = w0;
                *(uint2*)&sQ[pb0 + 8 * FST + jn * 8] = w1;
            }
            __syncwarp(qmask);
            #pragma unroll
            for (int u = 0; u < 2; u++) {
                const int ks = jp * 2 + u;
                uint32_t pa[4];
                const int base = pabase + ks * 8;
                pa[0] = sQ[base];
                pa[1] = sQ[base + 8 * FST];
                pa[2] = sQ[base + 4];
                pa[3] = sQ[base + 8 * FST + 4];
                #pragma unroll
                for (int dt = 0; dt < 8; dt++) {
                    const int vb = (ks * 8 + tig) * VST + dt * 8 + gid;
                    mma8(o[dt], pa, sV[vb], sV[vb + 4 * VST]);
                }
            }
        }
        rs0 += __shfl_xor_sync(0xffffffffu, rs0, 1);
        rs0 += __shfl_xor_sync(0xffffffffu, rs0, 2);
        rs1 += __shfl_xor_sync(0xffffffffu, rs1, 1);
        rs1 += __shfl_xor_sync(0xffffffffu, rs1, 2);
        lr0 = lr0 * al0 + rs0;
        lr1 = lr1 * al1 + rs1;

        stage ^= 1;
    }

    // epilogue (tf32-rounded stores: out-proj GEMM consumes raw)
    const float inv0 = 1.0f / lr0;
    const float inv1 = 1.0f / lr1;
    const int r0 = q0 + wrow + gid;
    #pragma unroll
    for (int dt = 0; dt < 8; dt++) {
        const int col = dt * 8 + 2 * tig;
        uint2 v0 = { f2tf32(o[dt][0] * inv0), f2tf32(o[dt][1] * inv0) };
        uint2 v1 = { f2tf32(o[dt][2] * inv1), f2tf32(o[dt][3] * inv1) };
        *(uint2*)&Ob[(size_t)r0 * NINNER + col]       = v0;
        *(uint2*)&Ob[(size_t)(r0 + 8) * NINNER + col] = v1;
    }
}

// ===========================================================================
extern "C" void kernel_launch(void* const* d_in, const int* in_sizes, int n_in,
                              void* d_out, int out_size)
{
    const float* X   = (const float*)d_in[0];
    const float* Wq  = (const float*)d_in[1];
    const float* Wkv = (const float*)d_in[2];
    const float* Wo  = (const float*)d_in[3];
    const float* bo  = (const float*)d_in[4];
    float* out = (float*)d_out;

    float *Xr, *QKV, *Ab, *Wqkv, *WoT;
    cudaGetSymbolAddress((void**)&Xr,    g_Xr);
    cudaGetSymbolAddress((void**)&QKV,   g_QKV);
    cudaGetSymbolAddress((void**)&Ab,    g_A);
    cudaGetSymbolAddress((void**)&Wqkv,  g_Wqkv);
    cudaGetSymbolAddress((void**)&WoT,   g_WoT);

    cudaFuncSetAttribute(gemm_mma, cudaFuncAttributeMaxDynamicSharedMemorySize,
                         GEMM_SMEM_BYTES);
    cudaFuncSetAttribute(flash_mma, cudaFuncAttributeMaxDynamicSharedMemorySize,
                         FLASH_SMEM_BYTES);

    // pre-round X to tf32 values (enables pure-cp.async GEMM loader)
    round_kernel<<<MTOT * DMODEL / 1024, 256>>>(X, Xr, MTOT * DMODEL);

    dim3 tb(32, 8);
    // fused weight buffer: rows 0-1023 = Wq^T * 0.125*log2e, 1024-3071 = Wkv^T
    transpose_kernel<<<dim3(NINNER / 32, DMODEL / 32), tb>>>(
        Wq,  Wqkv, DMODEL, NINNER, 0.125f * 1.4426950408889634f);
    transpose_kernel<<<dim3(2 * NINNER / 32, DMODEL / 32), tb>>>(
        Wkv, Wqkv + (size_t)NINNER * DMODEL, DMODEL, 2 * NINNER, 1.0f);
    transpose_kernel<<<dim3(DMODEL / 32, NINNER / 32), tb>>>(
        Wo,  WoT,  NINNER, DMODEL, 1.0f);

    // fused QKV = Xr @ Wqkv^T  (N=3072), tf32-rounded at store
    gemm_mma<<<dim3(FROWS / 128, MTOT / 128), 256, GEMM_SMEM_BYTES>>>(
        Xr, Wqkv, nullptr, QKV, MTOT, FROWS, DMODEL, 1);
    // attention (stores tf32-rounded A)
    flash_mma<<<dim3(NSEQ / 128, NB * NH), 256, FLASH_SMEM_BYTES>>>(QKV, Ab);
    // out = A @ Wo + bo (full fp32 store)
    gemm_mma<<<dim3(DMODEL / 128, MTOT / 128), 256, GEMM_SMEM_BYTES>>>(
        Ab, WoT, bo, out, MTOT, DMODEL, NINNER, 0);
}